// round 7
// baseline (speedup 1.0000x reference)
#include <cuda_runtime.h>
#include <cuda_bf16.h>
#include <cstdint>

#define Bb 8
#define Nn 2048
#define Kk 256
#define Ff 128
#define NCH 32
#define CSZ 64

// -------- scratch (device globals; no allocation allowed) --------
__device__ float g_Wh[Bb*Nn*Ff];
__device__ float g_u [Bb*Nn];
__device__ float g_v [Bb*Nn];
__device__ float g_wa_i[Kk];
__device__ float g_wa_j[Kk];
__device__ int   g_kidx[Bb*Nn];
__device__ int   g_perm[Bb*Nn];
__device__ float g_Ej [Bb*Nn];
__device__ float g_Fj [Bb*Nn];
__device__ float g_PzE[Bb*Nn];
__device__ float g_PzF[Bb*Nn];
__device__ float g_PE [Bb*Nn*Ff];
__device__ float g_PF [Bb*Nn*Ff];
__device__ float g_chE[Bb*Ff*NCH];  // [b][f][chunk]
__device__ float g_chF[Bb*Ff*NCH];
__device__ float g_offE[Bb*NCH*Ff]; // [b][chunk][f]
__device__ float g_offF[Bb*NCH*Ff];
__device__ float g_TF [Bb*Ff];

// ================= helpers =================
__device__ __forceinline__ uint32_t smem_u32(const void* p){
    uint32_t a;
    asm("{ .reg .u64 t; cvta.to.shared.u64 t, %1; cvt.u32.u64 %0, t; }" : "=r"(a) : "l"(p));
    return a;
}
__device__ __forceinline__ void ldsm_x4(uint32_t* r, uint32_t addr){
    asm volatile("ldmatrix.sync.aligned.m8n8.x4.shared.b16 {%0,%1,%2,%3}, [%4];"
        : "=r"(r[0]),"=r"(r[1]),"=r"(r[2]),"=r"(r[3]) : "r"(addr));
}
__device__ __forceinline__ void ldsm_x4t(uint32_t* r, uint32_t addr){
    asm volatile("ldmatrix.sync.aligned.m8n8.x4.trans.shared.b16 {%0,%1,%2,%3}, [%4];"
        : "=r"(r[0]),"=r"(r[1]),"=r"(r[2]),"=r"(r[3]) : "r"(addr));
}
__device__ __forceinline__ void mma16816(float* d, const uint32_t* a, const uint32_t* b){
    asm volatile("mma.sync.aligned.m16n8k16.row.col.f32.bf16.bf16.f32 "
        "{%0,%1,%2,%3}, {%4,%5,%6,%7}, {%8,%9}, {%0,%1,%2,%3};"
        : "+f"(d[0]),"+f"(d[1]),"+f"(d[2]),"+f"(d[3])
        : "r"(a[0]),"r"(a[1]),"r"(a[2]),"r"(a[3]), "r"(b[0]),"r"(b[1]));
}

// smem layout for gemm (bytes), double-buffered pings
#define AP 72                       // A row pitch in bf16
#define BP 136                      // B row pitch in bf16
#define OFF_AHI 0
#define OFF_ALO 18432
#define OFF_BHI 36864
#define OFF_BLO 54272
#define PING_SZ 71680
#define SM_PHASE1 (2*PING_SZ)       // 143360

// ======== Kernel W0: wa = W @ a ========
__global__ void wa_kernel(const float* __restrict__ W,
                          const float* __restrict__ ai, const float* __restrict__ aj){
    int wid = (blockIdx.x*256 + threadIdx.x) >> 5;
    int lane = threadIdx.x & 31;
    const float* wr = &W[(size_t)wid*Ff];
    float pu=0.f, pv=0.f;
    #pragma unroll
    for (int q=0;q<4;q++){
        int n = lane + q*32;
        float w = wr[n];
        pu = fmaf(w, ai[n], pu);
        pv = fmaf(w, aj[n], pv);
    }
    #pragma unroll
    for (int s=16;s>0;s>>=1){
        pu += __shfl_xor_sync(0xffffffffu, pu, s);
        pv += __shfl_xor_sync(0xffffffffu, pv, s);
    }
    if (lane==0){ g_wa_i[wid]=pu; g_wa_j[wid]=pv; }
}

// ======== Kernel W1: u,v = h @ wa (warp per row) ========
__global__ __launch_bounds__(256)
void uv_kernel(const float* __restrict__ h){
    int row = blockIdx.x*8 + (threadIdx.x>>5);
    int lane = threadIdx.x & 31;
    const float4* hr = (const float4*)&h[(size_t)row*Kk];
    float pu=0.f, pv=0.f;
    #pragma unroll
    for (int q=0;q<2;q++){
        int i4 = lane + q*32;
        float4 x = hr[i4];
        const float* wi = &g_wa_i[i4*4];
        const float* wj = &g_wa_j[i4*4];
        pu = fmaf(x.x,wi[0],fmaf(x.y,wi[1],fmaf(x.z,wi[2],fmaf(x.w,wi[3],pu))));
        pv = fmaf(x.x,wj[0],fmaf(x.y,wj[1],fmaf(x.z,wj[2],fmaf(x.w,wj[3],pv))));
    }
    #pragma unroll
    for (int s=16;s>0;s>>=1){
        pu += __shfl_xor_sync(0xffffffffu, pu, s);
        pv += __shfl_xor_sync(0xffffffffu, pv, s);
    }
    if (lane==0){ g_u[row]=pu; g_v[row]=pv; }
}

// ============ device fn: stage one K-chunk (split bf16) into ping p ============
__device__ __forceinline__ void stage_chunk(char* smem, const float* __restrict__ hB,
                                            const float* __restrict__ W,
                                            int kc, int p, int tid){
    char* base = smem + p*PING_SZ;
    // A: 128 rows x 64 k
    for (int idx = tid; idx < 128*32; idx += 256){
        int r = idx >> 5, kp = idx & 31;
        float2 x = *(const float2*)&hB[(size_t)r*Kk + kc + kp*2];
        __nv_bfloat162 hi, lo;
        hi.x = __float2bfloat16(x.x); lo.x = __float2bfloat16(x.x - __bfloat162float(hi.x));
        hi.y = __float2bfloat16(x.y); lo.y = __float2bfloat16(x.y - __bfloat162float(hi.y));
        uint32_t off = (uint32_t)((r*AP + kp*2) * 2);
        *(__nv_bfloat162*)(base + OFF_AHI + off) = hi;
        *(__nv_bfloat162*)(base + OFF_ALO + off) = lo;
    }
    // B: 64 k x 128 n
    for (int idx = tid; idx < 64*64; idx += 256){
        int k = idx >> 6, np = idx & 63;
        float2 x = *(const float2*)&W[(size_t)(kc+k)*Ff + np*2];
        __nv_bfloat162 hi, lo;
        hi.x = __float2bfloat16(x.x); lo.x = __float2bfloat16(x.x - __bfloat162float(hi.x));
        hi.y = __float2bfloat16(x.y); lo.y = __float2bfloat16(x.y - __bfloat162float(hi.y));
        uint32_t off = (uint32_t)((k*BP + np*2) * 2);
        *(__nv_bfloat162*)(base + OFF_BHI + off) = hi;
        *(__nv_bfloat162*)(base + OFF_BLO + off) = lo;
    }
}

// ============ Phase 1: heterogeneous grid: gemm (0..127) || sort (128..135) ====
__global__ __launch_bounds__(256)
void phase1(const float* __restrict__ h, const float* __restrict__ W){
    extern __shared__ char smem[];
    int tid = threadIdx.x;

    if (blockIdx.x < 128){
        // ----------------- GEMM tile, double-buffered -----------------
        uint32_t sb = smem_u32(smem);
        int wid = tid >> 5, lane = tid & 31;
        int warp_m = wid & 1, warp_n = wid >> 1;
        int b = blockIdx.x >> 4;
        int row0 = (blockIdx.x & 15) * 128;
        const float* hB = h + ((size_t)b*Nn + row0) * Kk;

        float acc[4][4][4];
        #pragma unroll
        for (int mt=0;mt<4;mt++)
            #pragma unroll
            for (int nt=0;nt<4;nt++)
                #pragma unroll
                for (int q=0;q<4;q++) acc[mt][nt][q]=0.f;

        int within = lane & 7, blk = lane >> 3;
        uint32_t aRel = (uint32_t)(((warp_m*64 + within + (blk&1)*8) * AP + (blk>>1)*8) * 2);
        uint32_t bRel = (uint32_t)(((within + (blk&1)*8) * BP + warp_n*32 + (blk>>1)*8) * 2);

        stage_chunk(smem, hB, W, 0, 0, tid);
        __syncthreads();

        for (int c = 0; c < 4; c++){
            int cur = c & 1;
            uint32_t pb = sb + cur*PING_SZ;
            uint32_t aBase = pb + OFF_AHI + aRel;
            uint32_t bBase = pb + OFF_BHI + bRel;
            #pragma unroll
            for (int ks = 0; ks < 4; ks++){
                uint32_t ah[4][4], al[4][4];
                #pragma unroll
                for (int mt=0;mt<4;mt++){
                    uint32_t ad = aBase + (uint32_t)(mt*16*AP*2 + ks*32);
                    ldsm_x4 (ah[mt], ad);
                    ldsm_x4 (al[mt], ad + (OFF_ALO-OFF_AHI));
                }
                uint32_t bh[2][4], bl[2][4];
                #pragma unroll
                for (int np=0;np<2;np++){
                    uint32_t bd = bBase + (uint32_t)(np*32 + ks*16*BP*2);
                    ldsm_x4t(bh[np], bd);
                    ldsm_x4t(bl[np], bd + (OFF_BLO-OFF_BHI));
                }
                #pragma unroll
                for (int mt=0;mt<4;mt++){
                    #pragma unroll
                    for (int nt=0;nt<4;nt++){
                        const uint32_t* pbh = &bh[nt>>1][(nt&1)*2];
                        const uint32_t* pbl = &bl[nt>>1][(nt&1)*2];
                        mma16816(acc[mt][nt], ah[mt], pbh);
                        mma16816(acc[mt][nt], ah[mt], pbl);
                        mma16816(acc[mt][nt], al[mt], pbh);
                    }
                }
            }
            if (c < 3) stage_chunk(smem, hB, W, (c+1)*64, cur^1, tid);
            __syncthreads();
        }

        int g = lane >> 2, tig = lane & 3;
        #pragma unroll
        for (int mt=0;mt<4;mt++){
            int r0a = row0 + warp_m*64 + mt*16 + g;
            #pragma unroll
            for (int nt=0;nt<4;nt++){
                int col = warp_n*32 + nt*8 + 2*tig;
                float2 d01; d01.x = acc[mt][nt][0]; d01.y = acc[mt][nt][1];
                float2 d23; d23.x = acc[mt][nt][2]; d23.y = acc[mt][nt][3];
                *(float2*)&g_Wh[((size_t)b*Nn + r0a    )*Ff + col] = d01;
                *(float2*)&g_Wh[((size_t)b*Nn + r0a + 8)*Ff + col] = d23;
            }
        }
    } else {
        // ----------------- per-batch sort + scans + k-index -----------------
        float* skey = (float*)(smem);
        int*   sidx = (int*)  (smem + 8192);
        float* sa   = (float*)(smem + 16384);
        float* sb2  = (float*)(smem + 24576);
        float* st   = (float*)(smem + 32768);
        int b = blockIdx.x - 128;

        for (int e=tid; e<2048; e+=256){ skey[e] = -g_v[b*Nn+e]; sidx[e]=e; }
        __syncthreads();

        for (int k=2;k<=2048;k<<=1){
            for (int j=k>>1;j>0;j>>=1){
                for (int e=tid;e<2048;e+=256){
                    int ixj = e ^ j;
                    if (ixj > e){
                        bool up = ((e & k) == 0);
                        float a=skey[e], c=skey[ixj];
                        if ((a > c) == up){
                            skey[e]=c; skey[ixj]=a;
                            int t1=sidx[e]; sidx[e]=sidx[ixj]; sidx[ixj]=t1;
                        }
                    }
                }
                __syncthreads();
            }
        }

        for (int e=tid;e<2048;e+=256){
            float vv = -skey[e];
            float Ejv = __expf(vv);
            float Fjv = __expf(0.01f*vv);
            g_perm[b*Nn+e]=sidx[e];
            g_Ej  [b*Nn+e]=Ejv; g_Fj  [b*Nn+e]=Fjv;
            sa[e]=Ejv; sb2[e]=Fjv;
        }
        __syncthreads();

        { // scan Ej
            float* src = sa; float* dst = st;
            for (int d=1; d<2048; d<<=1){
                for (int e=tid;e<2048;e+=256)
                    dst[e] = src[e] + (e>=d ? src[e-d] : 0.f);
                __syncthreads();
                float* tp=src; src=dst; dst=tp;
            }
            for (int e=tid;e<2048;e+=256) g_PzE[b*Nn+e] = src[e];
            __syncthreads();
        }
        { // scan Fj
            float* src = sb2; float* dst = sa;
            for (int d=1; d<2048; d<<=1){
                for (int e=tid;e<2048;e+=256)
                    dst[e] = src[e] + (e>=d ? src[e-d] : 0.f);
                __syncthreads();
                float* tp=src; src=dst; dst=tp;
            }
            for (int e=tid;e<2048;e+=256) g_PzF[b*Nn+e] = src[e];
            __syncthreads();
        }
        // k-index per row: count of sorted keys < u_row (skey untouched since sort)
        for (int r=tid; r<2048; r+=256){
            float uu = g_u[b*Nn+r];
            int lo=0, hi=2048;
            while (lo<hi){ int mid=(lo+hi)>>1; if (skey[mid] < uu) lo=mid+1; else hi=mid; }
            g_kidx[b*Nn+r] = lo;
        }
    }
}

// ============ Kernel C1: chunk-local vector prefixes of Ej*Wh, Fj*Wh ==========
__global__ void prefix_chunks() {
    __shared__ int   sperm[CSZ];
    __shared__ float sE[CSZ], sF[CSZ];
    int b = blockIdx.y, ch = blockIdx.x, f = threadIdx.x; // 128 thr
    int base = ch*CSZ;
    if (f < CSZ){
        sperm[f]=g_perm[b*Nn+base+f];
        sE[f]=g_Ej[b*Nn+base+f];
        sF[f]=g_Fj[b*Nn+base+f];
    }
    __syncthreads();
    float ae=0.f, af=0.f;
    #pragma unroll 4
    for (int m=0;m<CSZ;m++){
        int j = sperm[m];
        float w = g_Wh[((size_t)b*Nn + j)*Ff + f];
        ae = fmaf(sE[m], w, ae);
        af = fmaf(sF[m], w, af);
        size_t o = ((size_t)b*Nn + base + m)*Ff + f;
        g_PE[o]=ae; g_PF[o]=af;
    }
    g_chE[((size_t)b*Ff+f)*NCH+ch]=ae;
    g_chF[((size_t)b*Ff+f)*NCH+ch]=af;
}

// ======== Kernel C2: warp-parallel exclusive scan of chunk totals =============
__global__ void scan_chunks(){
    int b=blockIdx.x;
    int lane=threadIdx.x, ty=threadIdx.y;
    int f = blockIdx.y*32 + ty;
    float ev = g_chE[((size_t)b*Ff+f)*NCH + lane];
    float fv = g_chF[((size_t)b*Ff+f)*NCH + lane];
    float ie = ev, iff = fv;
    #pragma unroll
    for (int s=1;s<32;s<<=1){
        float te = __shfl_up_sync(0xffffffffu, ie, s);
        float tf = __shfl_up_sync(0xffffffffu, iff, s);
        if (lane>=s){ ie+=te; iff+=tf; }
    }
    g_offE[((size_t)b*NCH+lane)*Ff+f] = ie - ev;
    g_offF[((size_t)b*NCH+lane)*Ff+f] = iff - fv;
    if (lane==31) g_TF[b*Ff+f] = iff;
}

// ================= Kernel D: combine (k precomputed) ==========================
__global__ __launch_bounds__(1024)
void finalize(float* __restrict__ out){
    int b  = blockIdx.y;
    int tx = threadIdx.x;  // 128 (feature)
    int ty = threadIdx.y;  // 8 rows per block
    int row = blockIdx.x*8 + ty;

    int k = g_kidx[b*Nn+row];
    float uu = g_u[b*Nn+row];
    float Ei = __expf(uu), Fi = __expf(0.01f*uu);
    float TFf = g_TF[b*Ff+tx];
    float TzF = g_PzF[b*Nn + 2047];

    float pe=0.f, pf=0.f, pze=0.f, pzf=0.f;
    if (k>0){
        int km = k-1, c = km>>6;
        size_t o = ((size_t)b*Nn+km)*Ff+tx;
        pe  = g_PE[o] + g_offE[(b*NCH+c)*Ff+tx];
        pf  = g_PF[o] + g_offF[(b*NCH+c)*Ff+tx];
        pze = g_PzE[b*Nn+km];
        pzf = g_PzF[b*Nn+km];
    }
    float num = Ei*pe + Fi*(TFf - pf);
    float den = Ei*pze + Fi*(TzF - pzf);
    out[((size_t)b*Nn+row)*Ff+tx] = num/den;
}

// ================= launch =================
extern "C" void kernel_launch(void* const* d_in, const int* in_sizes, int n_in,
                              void* d_out, int out_size) {
    const float* h  = (const float*)d_in[0];
    const float* W  = (const float*)d_in[1];
    const float* ai = (const float*)d_in[2];
    const float* aj = (const float*)d_in[3];
    float* out = (float*)d_out;

    cudaFuncSetAttribute(phase1, cudaFuncAttributeMaxDynamicSharedMemorySize, SM_PHASE1);

    wa_kernel    <<<32, 256>>>(W, ai, aj);
    uv_kernel    <<<2048, 256>>>(h);
    phase1       <<<136, 256, SM_PHASE1>>>(h, W);
    prefix_chunks<<<dim3(NCH, Bb), 128>>>();
    scan_chunks  <<<dim3(Bb, 4), dim3(32,32)>>>();
    finalize     <<<dim3(Nn/8, Bb), dim3(128,8)>>>(out);
}

// round 9
// speedup vs baseline: 1.8756x; 1.8756x over previous
#include <cuda_runtime.h>
#include <cuda_bf16.h>
#include <cstdint>

#define Bb 8
#define Nn 2048
#define Kk 256
#define Ff 128
#define NCH 32
#define CSZ 64

// -------- scratch (device globals) --------
__device__ float g_Wh[Bb*Nn*Ff];
__device__ float g_u [Bb*Nn];
__device__ float g_v [Bb*Nn];
__device__ float g_wa_i[Kk];
__device__ float g_wa_j[Kk];
__device__ int   g_kidx[Bb*Nn];
__device__ int   g_perm[Bb*Nn];
__device__ float g_Ej [Bb*Nn];
__device__ float g_Fj [Bb*Nn];
__device__ float g_PzE[Bb*Nn];      // chunk-local inclusive scalar prefixes
__device__ float g_PzF[Bb*Nn];
__device__ float g_PE [Bb*Nn*Ff];
__device__ float g_PF [Bb*Nn*Ff];
__device__ float g_chE[Bb*Ff*NCH];  // [b][f][chunk]
__device__ float g_chF[Bb*Ff*NCH];
__device__ float g_chzE[Bb*NCH];    // scalar chunk totals
__device__ float g_chzF[Bb*NCH];
__device__ float g_offE[Bb*NCH*Ff]; // [b][chunk][f] exclusive offsets
__device__ float g_offF[Bb*NCH*Ff];
__device__ float g_offzE[Bb*NCH];
__device__ float g_offzF[Bb*NCH];
__device__ float g_TF [Bb*Ff];
__device__ float g_TzF[Bb];

// ================= helpers =================
__device__ __forceinline__ uint32_t smem_u32(const void* p){
    uint32_t a;
    asm("{ .reg .u64 t; cvta.to.shared.u64 t, %1; cvt.u32.u64 %0, t; }" : "=r"(a) : "l"(p));
    return a;
}
__device__ __forceinline__ void ldsm_x4(uint32_t* r, uint32_t addr){
    asm volatile("ldmatrix.sync.aligned.m8n8.x4.shared.b16 {%0,%1,%2,%3}, [%4];"
        : "=r"(r[0]),"=r"(r[1]),"=r"(r[2]),"=r"(r[3]) : "r"(addr));
}
__device__ __forceinline__ void ldsm_x4t(uint32_t* r, uint32_t addr){
    asm volatile("ldmatrix.sync.aligned.m8n8.x4.trans.shared.b16 {%0,%1,%2,%3}, [%4];"
        : "=r"(r[0]),"=r"(r[1]),"=r"(r[2]),"=r"(r[3]) : "r"(addr));
}
__device__ __forceinline__ void mma16816(float* d, const uint32_t* a, const uint32_t* b){
    asm volatile("mma.sync.aligned.m16n8k16.row.col.f32.bf16.bf16.f32 "
        "{%0,%1,%2,%3}, {%4,%5,%6,%7}, {%8,%9}, {%0,%1,%2,%3};"
        : "+f"(d[0]),"+f"(d[1]),"+f"(d[2]),"+f"(d[3])
        : "r"(a[0]),"r"(a[1]),"r"(a[2]),"r"(a[3]), "r"(b[0]),"r"(b[1]));
}

// smem layout for gemm (bytes), double-buffered
#define AP 72
#define BP 136
#define OFF_AHI 0
#define OFF_ALO 18432
#define OFF_BHI 36864
#define OFF_BLO 54272
#define PING_SZ 71680
#define SM_GEMM (2*PING_SZ)

// ======== Kernel W0: wa = W @ a ========
__global__ void wa_kernel(const float* __restrict__ W,
                          const float* __restrict__ ai, const float* __restrict__ aj){
    int wid = (blockIdx.x*256 + threadIdx.x) >> 5;
    int lane = threadIdx.x & 31;
    const float* wr = &W[(size_t)wid*Ff];
    float pu=0.f, pv=0.f;
    #pragma unroll
    for (int q=0;q<4;q++){
        int n = lane + q*32;
        float w = wr[n];
        pu = fmaf(w, ai[n], pu);
        pv = fmaf(w, aj[n], pv);
    }
    #pragma unroll
    for (int s=16;s>0;s>>=1){
        pu += __shfl_xor_sync(0xffffffffu, pu, s);
        pv += __shfl_xor_sync(0xffffffffu, pv, s);
    }
    if (lane==0){ g_wa_i[wid]=pu; g_wa_j[wid]=pv; }
}

// ======== Kernel W1: u,v = h @ wa (warp per row) ========
__global__ __launch_bounds__(256)
void uv_kernel(const float* __restrict__ h){
    int row = blockIdx.x*8 + (threadIdx.x>>5);
    int lane = threadIdx.x & 31;
    const float4* hr = (const float4*)&h[(size_t)row*Kk];
    float pu=0.f, pv=0.f;
    #pragma unroll
    for (int q=0;q<2;q++){
        int i4 = lane + q*32;
        float4 x = hr[i4];
        const float* wi = &g_wa_i[i4*4];
        const float* wj = &g_wa_j[i4*4];
        pu = fmaf(x.x,wi[0],fmaf(x.y,wi[1],fmaf(x.z,wi[2],fmaf(x.w,wi[3],pu))));
        pv = fmaf(x.x,wj[0],fmaf(x.y,wj[1],fmaf(x.z,wj[2],fmaf(x.w,wj[3],pv))));
    }
    #pragma unroll
    for (int s=16;s>0;s>>=1){
        pu += __shfl_xor_sync(0xffffffffu, pu, s);
        pv += __shfl_xor_sync(0xffffffffu, pv, s);
    }
    if (lane==0){ g_u[row]=pu; g_v[row]=pv; }
}

// ======== Kernel R: ranks + branch index by brute-force count ========
// grid (16, Bb), block 128; thread = one row
__global__ __launch_bounds__(128)
void rank_kernel(){
    __shared__ __align__(16) float sv[2048];
    int b = blockIdx.y, tid = threadIdx.x;
    for (int e=tid; e<2048; e+=128) sv[e] = g_v[b*Nn+e];
    __syncthreads();

    int i = blockIdx.x*128 + tid;
    float vi  = sv[i];
    float nui = -g_u[b*Nn+i];
    int rnk=0, ck=0;
    const float4* sv4 = (const float4*)sv;
    #pragma unroll 4
    for (int q=0; q<512; q++){
        float4 x = sv4[q];
        int m0 = q*4;
        rnk += (x.x>vi) + (x.y>vi) + (x.z>vi) + (x.w>vi);
        ck  += (x.x>nui)+ (x.y>nui)+ (x.z>nui)+ (x.w>nui);
        rnk += ((x.x==vi)&&(m0  <i)) + ((x.y==vi)&&(m0+1<i))
             + ((x.z==vi)&&(m0+2<i)) + ((x.w==vi)&&(m0+3<i));
    }
    g_kidx[b*Nn+i] = ck;
    g_perm[b*Nn+rnk] = i;
    g_Ej[b*Nn+rnk] = __expf(vi);
    g_Fj[b*Nn+rnk] = __expf(0.01f*vi);
}

// ============ stage one K-chunk (split bf16) into ping p ============
__device__ __forceinline__ void stage_chunk(char* smem, const float* __restrict__ hB,
                                            const float* __restrict__ W,
                                            int kc, int p, int tid){
    char* base = smem + p*PING_SZ;
    for (int idx = tid; idx < 128*32; idx += 256){
        int r = idx >> 5, kp = idx & 31;
        float2 x = *(const float2*)&hB[(size_t)r*Kk + kc + kp*2];
        __nv_bfloat162 hi, lo;
        hi.x = __float2bfloat16(x.x); lo.x = __float2bfloat16(x.x - __bfloat162float(hi.x));
        hi.y = __float2bfloat16(x.y); lo.y = __float2bfloat16(x.y - __bfloat162float(hi.y));
        uint32_t off = (uint32_t)((r*AP + kp*2) * 2);
        *(__nv_bfloat162*)(base + OFF_AHI + off) = hi;
        *(__nv_bfloat162*)(base + OFF_ALO + off) = lo;
    }
    for (int idx = tid; idx < 64*64; idx += 256){
        int k = idx >> 6, np = idx & 63;
        float2 x = *(const float2*)&W[(size_t)(kc+k)*Ff + np*2];
        __nv_bfloat162 hi, lo;
        hi.x = __float2bfloat16(x.x); lo.x = __float2bfloat16(x.x - __bfloat162float(hi.x));
        hi.y = __float2bfloat16(x.y); lo.y = __float2bfloat16(x.y - __bfloat162float(hi.y));
        uint32_t off = (uint32_t)((k*BP + np*2) * 2);
        *(__nv_bfloat162*)(base + OFF_BHI + off) = hi;
        *(__nv_bfloat162*)(base + OFF_BLO + off) = lo;
    }
}

// ============ Kernel A: Wh = h@W (split-bf16 mma.sync, double-buffered) ========
__global__ __launch_bounds__(256)
void gemm_mma(const float* __restrict__ h, const float* __restrict__ W){
    extern __shared__ char smem[];
    uint32_t sb = smem_u32(smem);
    int tid = threadIdx.x;
    int wid = tid >> 5, lane = tid & 31;
    int warp_m = wid & 1, warp_n = wid >> 1;
    int b = blockIdx.y;
    int row0 = blockIdx.x * 128;
    const float* hB = h + ((size_t)b*Nn + row0) * Kk;

    float acc[4][4][4];
    #pragma unroll
    for (int mt=0;mt<4;mt++)
        #pragma unroll
        for (int nt=0;nt<4;nt++)
            #pragma unroll
            for (int q=0;q<4;q++) acc[mt][nt][q]=0.f;

    int within = lane & 7, blk = lane >> 3;
    uint32_t aRel = (uint32_t)(((warp_m*64 + within + (blk&1)*8) * AP + (blk>>1)*8) * 2);
    uint32_t bRel = (uint32_t)(((within + (blk&1)*8) * BP + warp_n*32 + (blk>>1)*8) * 2);

    stage_chunk(smem, hB, W, 0, 0, tid);
    __syncthreads();

    for (int c = 0; c < 4; c++){
        int cur = c & 1;
        uint32_t pb = sb + cur*PING_SZ;
        uint32_t aBase = pb + OFF_AHI + aRel;
        uint32_t bBase = pb + OFF_BHI + bRel;
        #pragma unroll
        for (int ks = 0; ks < 4; ks++){
            uint32_t ah[4][4], al[4][4];
            #pragma unroll
            for (int mt=0;mt<4;mt++){
                uint32_t ad = aBase + (uint32_t)(mt*16*AP*2 + ks*32);
                ldsm_x4 (ah[mt], ad);
                ldsm_x4 (al[mt], ad + (OFF_ALO-OFF_AHI));
            }
            uint32_t bh[2][4], bl[2][4];
            #pragma unroll
            for (int np=0;np<2;np++){
                uint32_t bd = bBase + (uint32_t)(np*32 + ks*16*BP*2);
                ldsm_x4t(bh[np], bd);
                ldsm_x4t(bl[np], bd + (OFF_BLO-OFF_BHI));
            }
            #pragma unroll
            for (int mt=0;mt<4;mt++){
                #pragma unroll
                for (int nt=0;nt<4;nt++){
                    const uint32_t* pbh = &bh[nt>>1][(nt&1)*2];
                    const uint32_t* pbl = &bl[nt>>1][(nt&1)*2];
                    mma16816(acc[mt][nt], ah[mt], pbh);
                    mma16816(acc[mt][nt], ah[mt], pbl);
                    mma16816(acc[mt][nt], al[mt], pbh);
                }
            }
        }
        if (c < 3) stage_chunk(smem, hB, W, (c+1)*64, cur^1, tid);
        __syncthreads();
    }

    int g = lane >> 2, tig = lane & 3;
    #pragma unroll
    for (int mt=0;mt<4;mt++){
        int r0a = row0 + warp_m*64 + mt*16 + g;
        #pragma unroll
        for (int nt=0;nt<4;nt++){
            int col = warp_n*32 + nt*8 + 2*tig;
            float2 d01; d01.x = acc[mt][nt][0]; d01.y = acc[mt][nt][1];
            float2 d23; d23.x = acc[mt][nt][2]; d23.y = acc[mt][nt][3];
            *(float2*)&g_Wh[((size_t)b*Nn + r0a    )*Ff + col] = d01;
            *(float2*)&g_Wh[((size_t)b*Nn + r0a + 8)*Ff + col] = d23;
        }
    }
}

// ============ Kernel C1: chunk-local prefixes (vector + scalar) ==========
__global__ __launch_bounds__(128)
void prefix_chunks() {
    __shared__ int   sperm[CSZ];
    __shared__ float sE[CSZ], sF[CSZ];
    int b = blockIdx.y, ch = blockIdx.x, f = threadIdx.x; // 128 thr
    int base = ch*CSZ;
    if (f < CSZ){
        sperm[f]=g_perm[b*Nn+base+f];
        sE[f]=g_Ej[b*Nn+base+f];
        sF[f]=g_Fj[b*Nn+base+f];
    }
    __syncthreads();

    // prefetch all 64 Wh values for this feature (independent LDGs)
    float wreg[CSZ];
    #pragma unroll
    for (int m=0;m<CSZ;m++)
        wreg[m] = g_Wh[((size_t)b*Nn + sperm[m])*Ff + f];

    // warp 0: scalar inclusive scans of sE/sF over the 64-chunk
    if (f < 32){
        float e0=sE[f], e1=sE[f+32], f0=sF[f], f1=sF[f+32];
        float pe0=e0, pe1=e1, pf0=f0, pf1=f1;
        #pragma unroll
        for (int s=1;s<32;s<<=1){
            float a=__shfl_up_sync(0xffffffffu, pe0, s);
            float bq=__shfl_up_sync(0xffffffffu, pe1, s);
            float cq=__shfl_up_sync(0xffffffffu, pf0, s);
            float d=__shfl_up_sync(0xffffffffu, pf1, s);
            if (f>=s){ pe0+=a; pe1+=bq; pf0+=cq; pf1+=d; }
        }
        float te0=__shfl_sync(0xffffffffu, pe0, 31);
        float tf0=__shfl_sync(0xffffffffu, pf0, 31);
        pe1 += te0; pf1 += tf0;
        g_PzE[b*Nn+base+f]    = pe0;
        g_PzE[b*Nn+base+32+f] = pe1;
        g_PzF[b*Nn+base+f]    = pf0;
        g_PzF[b*Nn+base+32+f] = pf1;
        if (f==31){ g_chzE[b*NCH+ch]=pe1; g_chzF[b*NCH+ch]=pf1; }
    }

    float ae=0.f, af=0.f;
    #pragma unroll
    for (int m=0;m<CSZ;m++){
        ae = fmaf(sE[m], wreg[m], ae);
        af = fmaf(sF[m], wreg[m], af);
        size_t o = ((size_t)b*Nn + base + m)*Ff + f;
        g_PE[o]=ae; g_PF[o]=af;
    }
    g_chE[((size_t)b*Ff+f)*NCH+ch]=ae;
    g_chF[((size_t)b*Ff+f)*NCH+ch]=af;
}

// ======== Kernel C2: scans of chunk totals (vector + scalar) =============
__global__ void scan_chunks(){
    int b=blockIdx.x;
    int lane=threadIdx.x, ty=threadIdx.y;
    int f = blockIdx.y*32 + ty;
    float ev = g_chE[((size_t)b*Ff+f)*NCH + lane];
    float fv = g_chF[((size_t)b*Ff+f)*NCH + lane];
    float ie = ev, iff = fv;
    #pragma unroll
    for (int s=1;s<32;s<<=1){
        float te = __shfl_up_sync(0xffffffffu, ie, s);
        float tf = __shfl_up_sync(0xffffffffu, iff, s);
        if (lane>=s){ ie+=te; iff+=tf; }
    }
    g_offE[((size_t)b*NCH+lane)*Ff+f] = ie - ev;
    g_offF[((size_t)b*NCH+lane)*Ff+f] = iff - fv;
    if (lane==31) g_TF[b*Ff+f] = iff;

    if (blockIdx.y==0 && ty==0){
        float ze = g_chzE[b*NCH+lane];
        float zf = g_chzF[b*NCH+lane];
        float ize=ze, izf=zf;
        #pragma unroll
        for (int s=1;s<32;s<<=1){
            float a=__shfl_up_sync(0xffffffffu, ize, s);
            float c=__shfl_up_sync(0xffffffffu, izf, s);
            if (lane>=s){ ize+=a; izf+=c; }
        }
        g_offzE[b*NCH+lane] = ize - ze;
        g_offzF[b*NCH+lane] = izf - zf;
        if (lane==31) g_TzF[b] = izf;
    }
}

// ================= Kernel D: combine ==========================
__global__ __launch_bounds__(1024)
void finalize(float* __restrict__ out){
    int b  = blockIdx.y;
    int tx = threadIdx.x;  // 128 (feature)
    int ty = threadIdx.y;  // 8 rows per block
    int row = blockIdx.x*8 + ty;

    int k = g_kidx[b*Nn+row];
    float uu = g_u[b*Nn+row];
    float Ei = __expf(uu), Fi = __expf(0.01f*uu);
    float TFf = g_TF[b*Ff+tx];
    float TzF = g_TzF[b];

    float pe=0.f, pf=0.f, pze=0.f, pzf=0.f;
    if (k>0){
        int km = k-1, c = km>>6;
        size_t o = ((size_t)b*Nn+km)*Ff+tx;
        pe  = g_PE[o] + g_offE[(b*NCH+c)*Ff+tx];
        pf  = g_PF[o] + g_offF[(b*NCH+c)*Ff+tx];
        pze = g_PzE[b*Nn+km] + g_offzE[b*NCH+c];
        pzf = g_PzF[b*Nn+km] + g_offzF[b*NCH+c];
    }
    float num = Ei*pe + Fi*(TFf - pf);
    float den = Ei*pze + Fi*(TzF - pzf);
    out[((size_t)b*Nn+row)*Ff+tx] = num/den;
}

// ================= launch =================
extern "C" void kernel_launch(void* const* d_in, const int* in_sizes, int n_in,
                              void* d_out, int out_size) {
    const float* h  = (const float*)d_in[0];
    const float* W  = (const float*)d_in[1];
    const float* ai = (const float*)d_in[2];
    const float* aj = (const float*)d_in[3];
    float* out = (float*)d_out;

    cudaFuncSetAttribute(gemm_mma, cudaFuncAttributeMaxDynamicSharedMemorySize, SM_GEMM);

    wa_kernel    <<<32, 256>>>(W, ai, aj);
    uv_kernel    <<<2048, 256>>>(h);
    rank_kernel  <<<dim3(16, Bb), 128>>>();
    gemm_mma     <<<dim3(Nn/128, Bb), 256, SM_GEMM>>>(h, W);
    prefix_chunks<<<dim3(NCH, Bb), 128>>>();
    scan_chunks  <<<dim3(Bb, 4), dim3(32,32)>>>();
    finalize     <<<dim3(Nn/8, Bb), dim3(128,8)>>>(out);
}

// round 15
// speedup vs baseline: 1.9117x; 1.0193x over previous
#include <cuda_runtime.h>
#include <cuda_bf16.h>
#include <cstdint>

#define Bb 8
#define Nn 2048
#define Kk 256
#define Ff 128
#define NCH 32
#define CSZ 64

// -------- scratch (device globals) --------
__device__ __align__(16) float g_Wh[Bb*Nn*Ff];
__device__ float g_u [Bb*Nn];
__device__ float g_v [Bb*Nn];
__device__ float g_wa_i[Kk];
__device__ float g_wa_j[Kk];
__device__ __align__(16) __nv_bfloat16 g_h_hi[Bb*Nn*Kk];
__device__ __align__(16) __nv_bfloat16 g_h_lo[Bb*Nn*Kk];
__device__ __align__(16) __nv_bfloat16 g_W_hi[Kk*Ff];
__device__ __align__(16) __nv_bfloat16 g_W_lo[Kk*Ff];
__device__ int   g_kidx[Bb*Nn];
__device__ int   g_perm[Bb*Nn];
__device__ float g_Ej [Bb*Nn];
__device__ float g_Fj [Bb*Nn];
__device__ float g_PzE[Bb*Nn];
__device__ float g_PzF[Bb*Nn];
__device__ float g_PE [Bb*Nn*Ff];
__device__ float g_PF [Bb*Nn*Ff];
__device__ float g_chE[Bb*Ff*NCH];
__device__ float g_chF[Bb*Ff*NCH];
__device__ float g_chzE[Bb*NCH];
__device__ float g_chzF[Bb*NCH];
__device__ float g_offE[Bb*NCH*Ff];
__device__ float g_offF[Bb*NCH*Ff];
__device__ float g_offzE[Bb*NCH];
__device__ float g_offzF[Bb*NCH];
__device__ float g_TF [Bb*Ff];
__device__ float g_TzF[Bb];

// ================= helpers =================
__device__ __forceinline__ uint32_t smem_u32(const void* p){
    uint32_t a;
    asm("{ .reg .u64 t; cvta.to.shared.u64 t, %1; cvt.u32.u64 %0, t; }" : "=r"(a) : "l"(p));
    return a;
}
__device__ __forceinline__ void ldsm_x4(uint32_t* r, uint32_t addr){
    asm volatile("ldmatrix.sync.aligned.m8n8.x4.shared.b16 {%0,%1,%2,%3}, [%4];"
        : "=r"(r[0]),"=r"(r[1]),"=r"(r[2]),"=r"(r[3]) : "r"(addr));
}
__device__ __forceinline__ void ldsm_x4t(uint32_t* r, uint32_t addr){
    asm volatile("ldmatrix.sync.aligned.m8n8.x4.trans.shared.b16 {%0,%1,%2,%3}, [%4];"
        : "=r"(r[0]),"=r"(r[1]),"=r"(r[2]),"=r"(r[3]) : "r"(addr));
}
__device__ __forceinline__ void mma16816(float* d, const uint32_t* a, const uint32_t* b){
    asm volatile("mma.sync.aligned.m16n8k16.row.col.f32.bf16.bf16.f32 "
        "{%0,%1,%2,%3}, {%4,%5,%6,%7}, {%8,%9}, {%0,%1,%2,%3};"
        : "+f"(d[0]),"+f"(d[1]),"+f"(d[2]),"+f"(d[3])
        : "r"(a[0]),"r"(a[1]),"r"(a[2]),"r"(a[3]), "r"(b[0]),"r"(b[1]));
}
__device__ __forceinline__ void cp16(uint32_t dst, const void* src){
    asm volatile("cp.async.cg.shared.global [%0], [%1], 16;" :: "r"(dst), "l"(src));
}
#define CP_COMMIT() asm volatile("cp.async.commit_group;" ::: "memory")
#define CP_WAIT(n)  asm volatile("cp.async.wait_group %0;" :: "n"(n) : "memory")

__device__ __forceinline__ void split_bf16(float x, __nv_bfloat16& hi, __nv_bfloat16& lo){
    hi = __float2bfloat16(x);
    lo = __float2bfloat16(x - __bfloat162float(hi));
}

// smem layout (bytes), double-buffered. A pitch 144B (72 bf16), B pitch 272B (136 bf16)
#define AP 72
#define BP 136
#define OFF_AHI 0
#define OFF_ALO 18432
#define OFF_BHI 36864
#define OFF_BLO 54272
#define PING_SZ 71680
#define SM_GEMM (2*PING_SZ)

// ======== Kernel W0: wa = W @ a  (+ convert W to split bf16) ========
__global__ void wa_kernel(const float* __restrict__ W,
                          const float* __restrict__ ai, const float* __restrict__ aj){
    int t = blockIdx.x*256 + threadIdx.x;
    {
        float4 x = *(const float4*)&W[(size_t)t*4];
        __nv_bfloat16 h0,l0,h1,l1,h2,l2,h3,l3;
        split_bf16(x.x,h0,l0); split_bf16(x.y,h1,l1);
        split_bf16(x.z,h2,l2); split_bf16(x.w,h3,l3);
        __nv_bfloat162* ph = (__nv_bfloat162*)&g_W_hi[(size_t)t*4];
        __nv_bfloat162* pl = (__nv_bfloat162*)&g_W_lo[(size_t)t*4];
        ph[0] = {h0,h1}; ph[1] = {h2,h3};
        pl[0] = {l0,l1}; pl[1] = {l2,l3};
    }
    int wid = t >> 5;
    int lane = threadIdx.x & 31;
    const float* wr = &W[(size_t)wid*Ff];
    float pu=0.f, pv=0.f;
    #pragma unroll
    for (int q=0;q<4;q++){
        int n = lane + q*32;
        float w = wr[n];
        pu = fmaf(w, ai[n], pu);
        pv = fmaf(w, aj[n], pv);
    }
    #pragma unroll
    for (int s=16;s>0;s>>=1){
        pu += __shfl_xor_sync(0xffffffffu, pu, s);
        pv += __shfl_xor_sync(0xffffffffu, pv, s);
    }
    if (lane==0){ g_wa_i[wid]=pu; g_wa_j[wid]=pv; }
}

// ======== Kernel W1: u,v = h @ wa (warp per row) + convert h to split bf16 ====
__global__ __launch_bounds__(256)
void uv_kernel(const float* __restrict__ h){
    int row = blockIdx.x*8 + (threadIdx.x>>5);
    int lane = threadIdx.x & 31;
    const float4* hr = (const float4*)&h[(size_t)row*Kk];
    float pu=0.f, pv=0.f;
    #pragma unroll
    for (int q=0;q<2;q++){
        int i4 = lane + q*32;
        float4 x = hr[i4];
        const float* wi = &g_wa_i[i4*4];
        const float* wj = &g_wa_j[i4*4];
        pu = fmaf(x.x,wi[0],fmaf(x.y,wi[1],fmaf(x.z,wi[2],fmaf(x.w,wi[3],pu))));
        pv = fmaf(x.x,wj[0],fmaf(x.y,wj[1],fmaf(x.z,wj[2],fmaf(x.w,wj[3],pv))));
        __nv_bfloat16 h0,l0,h1,l1,h2,l2,h3,l3;
        split_bf16(x.x,h0,l0); split_bf16(x.y,h1,l1);
        split_bf16(x.z,h2,l2); split_bf16(x.w,h3,l3);
        __nv_bfloat162* ph = (__nv_bfloat162*)&g_h_hi[(size_t)row*Kk + i4*4];
        __nv_bfloat162* pl = (__nv_bfloat162*)&g_h_lo[(size_t)row*Kk + i4*4];
        ph[0] = {h0,h1}; ph[1] = {h2,h3};
        pl[0] = {l0,l1}; pl[1] = {l2,l3};
    }
    #pragma unroll
    for (int s=16;s>0;s>>=1){
        pu += __shfl_xor_sync(0xffffffffu, pu, s);
        pv += __shfl_xor_sync(0xffffffffu, pv, s);
    }
    if (lane==0){ g_u[row]=pu; g_v[row]=pv; }
}

// ======== Kernel R: ranks + branch index by brute-force count ========
__global__ __launch_bounds__(128)
void rank_kernel(){
    __shared__ __align__(16) float sv[2048];
    int b = blockIdx.y, tid = threadIdx.x;
    for (int e=tid; e<2048; e+=128) sv[e] = g_v[b*Nn+e];
    __syncthreads();

    int i = blockIdx.x*128 + tid;
    float vi  = sv[i];
    float nui = -g_u[b*Nn+i];
    int rnk=0, ck=0;
    const float4* sv4 = (const float4*)sv;
    #pragma unroll 4
    for (int q=0; q<512; q++){
        float4 x = sv4[q];
        int m0 = q*4;
        rnk += (x.x>vi) + (x.y>vi) + (x.z>vi) + (x.w>vi);
        ck  += (x.x>nui)+ (x.y>nui)+ (x.z>nui)+ (x.w>nui);
        rnk += ((x.x==vi)&&(m0  <i)) + ((x.y==vi)&&(m0+1<i))
             + ((x.z==vi)&&(m0+2<i)) + ((x.w==vi)&&(m0+3<i));
    }
    g_kidx[b*Nn+i] = ck;
    g_perm[b*Nn+rnk] = i;
    g_Ej[b*Nn+rnk] = __expf(vi);
    g_Fj[b*Nn+rnk] = __expf(0.01f*vi);
}

// ============ async stage one K-chunk into ping p ============
__device__ __forceinline__ void stage_cp(uint32_t sb, const __nv_bfloat16* hHiB,
                                         const __nv_bfloat16* hLoB,
                                         int kc, int p, int tid){
    uint32_t base = sb + p*PING_SZ;
    // A: 128 rows x 64 k = 8 x16B per row
    #pragma unroll
    for (int i=0;i<4;i++){
        int idx = tid + i*256;          // 0..1023
        int r = idx >> 3, k16 = idx & 7;
        uint32_t dst = base + OFF_AHI + (uint32_t)(r*AP*2 + k16*16);
        cp16(dst, hHiB + (size_t)r*Kk + kc + k16*8);
        cp16(dst + (OFF_ALO-OFF_AHI), hLoB + (size_t)r*Kk + kc + k16*8);
    }
    // B: 64 k x 128 n = 16 x16B per row
    #pragma unroll
    for (int i=0;i<4;i++){
        int idx = tid + i*256;
        int k = idx >> 4, n16 = idx & 15;
        uint32_t dst = base + OFF_BHI + (uint32_t)(k*BP*2 + n16*16);
        cp16(dst, g_W_hi + (size_t)(kc+k)*Ff + n16*8);
        cp16(dst + (OFF_BLO-OFF_BHI), g_W_lo + (size_t)(kc+k)*Ff + n16*8);
    }
}

// ============ Kernel A: Wh = h@W (split-bf16 mma.sync + cp.async pipeline) ====
__global__ __launch_bounds__(256)
void gemm_mma(){
    extern __shared__ char smem[];
    uint32_t sb = smem_u32(smem);
    int tid = threadIdx.x;
    int wid = tid >> 5, lane = tid & 31;
    int warp_m = wid & 1, warp_n = wid >> 1;
    int b = blockIdx.y;
    int row0 = blockIdx.x * 128;
    const __nv_bfloat16* hHiB = g_h_hi + ((size_t)b*Nn + row0) * Kk;
    const __nv_bfloat16* hLoB = g_h_lo + ((size_t)b*Nn + row0) * Kk;

    float acc[4][4][4];
    #pragma unroll
    for (int mt=0;mt<4;mt++)
        #pragma unroll
        for (int nt=0;nt<4;nt++)
            #pragma unroll
            for (int q=0;q<4;q++) acc[mt][nt][q]=0.f;

    int within = lane & 7, blk = lane >> 3;
    uint32_t aRel = (uint32_t)(((warp_m*64 + within + (blk&1)*8) * AP + (blk>>1)*8) * 2);
    uint32_t bRel = (uint32_t)(((within + (blk&1)*8) * BP + warp_n*32 + (blk>>1)*8) * 2);

    stage_cp(sb, hHiB, hLoB, 0, 0, tid);
    CP_COMMIT();

    for (int c = 0; c < 4; c++){
        if (c < 3){
            stage_cp(sb, hHiB, hLoB, (c+1)*64, (c+1)&1, tid);
            CP_COMMIT();
            CP_WAIT(1);
        } else {
            CP_WAIT(0);
        }
        __syncthreads();

        uint32_t pb = sb + (c&1)*PING_SZ;
        uint32_t aBase = pb + OFF_AHI + aRel;
        uint32_t bBase = pb + OFF_BHI + bRel;
        #pragma unroll
        for (int ks = 0; ks < 4; ks++){
            uint32_t ah[4][4], al[4][4];
            #pragma unroll
            for (int mt=0;mt<4;mt++){
                uint32_t ad = aBase + (uint32_t)(mt*16*AP*2 + ks*32);
                ldsm_x4 (ah[mt], ad);
                ldsm_x4 (al[mt], ad + (OFF_ALO-OFF_AHI));
            }
            uint32_t bh[2][4], bl[2][4];
            #pragma unroll
            for (int np=0;np<2;np++){
                uint32_t bd = bBase + (uint32_t)(np*32 + ks*16*BP*2);
                ldsm_x4t(bh[np], bd);
                ldsm_x4t(bl[np], bd + (OFF_BLO-OFF_BHI));
            }
            #pragma unroll
            for (int mt=0;mt<4;mt++){
                #pragma unroll
                for (int nt=0;nt<4;nt++){
                    const uint32_t* pbh = &bh[nt>>1][(nt&1)*2];
                    const uint32_t* pbl = &bl[nt>>1][(nt&1)*2];
                    mma16816(acc[mt][nt], ah[mt], pbh);
                    mma16816(acc[mt][nt], ah[mt], pbl);
                    mma16816(acc[mt][nt], al[mt], pbh);
                }
            }
        }
        __syncthreads();
    }

    int g = lane >> 2, tig = lane & 3;
    #pragma unroll
    for (int mt=0;mt<4;mt++){
        int r0a = row0 + warp_m*64 + mt*16 + g;
        #pragma unroll
        for (int nt=0;nt<4;nt++){
            int col = warp_n*32 + nt*8 + 2*tig;
            float2 d01; d01.x = acc[mt][nt][0]; d01.y = acc[mt][nt][1];
            float2 d23; d23.x = acc[mt][nt][2]; d23.y = acc[mt][nt][3];
            *(float2*)&g_Wh[((size_t)b*Nn + r0a    )*Ff + col] = d01;
            *(float2*)&g_Wh[((size_t)b*Nn + r0a + 8)*Ff + col] = d23;
        }
    }
}

// ============ Kernel C1: chunk-local prefixes (vector + scalar) ==========
__global__ __launch_bounds__(128)
void prefix_chunks() {
    __shared__ int   sperm[CSZ];
    __shared__ float sE[CSZ], sF[CSZ];
    int b = blockIdx.y, ch = blockIdx.x, f = threadIdx.x; // 128 thr
    int base = ch*CSZ;
    if (f < CSZ){
        sperm[f]=g_perm[b*Nn+base+f];
        sE[f]=g_Ej[b*Nn+base+f];
        sF[f]=g_Fj[b*Nn+base+f];
    }
    __syncthreads();

    float wreg[CSZ];
    #pragma unroll
    for (int m=0;m<CSZ;m++)
        wreg[m] = g_Wh[((size_t)b*Nn + sperm[m])*Ff + f];

    if (f < 32){
        float e0=sE[f], e1=sE[f+32], f0=sF[f], f1=sF[f+32];
        float pe0=e0, pe1=e1, pf0=f0, pf1=f1;
        #pragma unroll
        for (int s=1;s<32;s<<=1){
            float a=__shfl_up_sync(0xffffffffu, pe0, s);
            float bq=__shfl_up_sync(0xffffffffu, pe1, s);
            float cq=__shfl_up_sync(0xffffffffu, pf0, s);
            float d=__shfl_up_sync(0xffffffffu, pf1, s);
            if (f>=s){ pe0+=a; pe1+=bq; pf0+=cq; pf1+=d; }
        }
        float te0=__shfl_sync(0xffffffffu, pe0, 31);
        float tf0=__shfl_sync(0xffffffffu, pf0, 31);
        pe1 += te0; pf1 += tf0;
        g_PzE[b*Nn+base+f]    = pe0;
        g_PzE[b*Nn+base+32+f] = pe1;
        g_PzF[b*Nn+base+f]    = pf0;
        g_PzF[b*Nn+base+32+f] = pf1;
        if (f==31){ g_chzE[b*NCH+ch]=pe1; g_chzF[b*NCH+ch]=pf1; }
    }

    float ae=0.f, af=0.f;
    #pragma unroll
    for (int m=0;m<CSZ;m++){
        ae = fmaf(sE[m], wreg[m], ae);
        af = fmaf(sF[m], wreg[m], af);
        size_t o = ((size_t)b*Nn + base + m)*Ff + f;
        g_PE[o]=ae; g_PF[o]=af;
    }
    g_chE[((size_t)b*Ff+f)*NCH+ch]=ae;
    g_chF[((size_t)b*Ff+f)*NCH+ch]=af;
}

// ======== Kernel C2: scans of chunk totals (vector + scalar) =============
__global__ void scan_chunks(){
    int b=blockIdx.x;
    int lane=threadIdx.x, ty=threadIdx.y;
    int f = blockIdx.y*32 + ty;
    float ev = g_chE[((size_t)b*Ff+f)*NCH + lane];
    float fv = g_chF[((size_t)b*Ff+f)*NCH + lane];
    float ie = ev, iff = fv;
    #pragma unroll
    for (int s=1;s<32;s<<=1){
        float te = __shfl_up_sync(0xffffffffu, ie, s);
        float tf = __shfl_up_sync(0xffffffffu, iff, s);
        if (lane>=s){ ie+=te; iff+=tf; }
    }
    g_offE[((size_t)b*NCH+lane)*Ff+f] = ie - ev;
    g_offF[((size_t)b*NCH+lane)*Ff+f] = iff - fv;
    if (lane==31) g_TF[b*Ff+f] = iff;

    if (blockIdx.y==0 && ty==0){
        float ze = g_chzE[b*NCH+lane];
        float zf = g_chzF[b*NCH+lane];
        float ize=ze, izf=zf;
        #pragma unroll
        for (int s=1;s<32;s<<=1){
            float a=__shfl_up_sync(0xffffffffu, ize, s);
            float c=__shfl_up_sync(0xffffffffu, izf, s);
            if (lane>=s){ ize+=a; izf+=c; }
        }
        g_offzE[b*NCH+lane] = ize - ze;
        g_offzF[b*NCH+lane] = izf - zf;
        if (lane==31) g_TzF[b] = izf;
    }
}

// ================= Kernel D: combine ==========================
__global__ __launch_bounds__(1024)
void finalize(float* __restrict__ out){
    int b  = blockIdx.y;
    int tx = threadIdx.x;  // 128 (feature)
    int ty = threadIdx.y;  // 8 rows per block
    int row = blockIdx.x*8 + ty;

    int k = g_kidx[b*Nn+row];
    float uu = g_u[b*Nn+row];
    float Ei = __expf(uu), Fi = __expf(0.01f*uu);
    float TFf = g_TF[b*Ff+tx];
    float TzF = g_TzF[b];

    float pe=0.f, pf=0.f, pze=0.f, pzf=0.f;
    if (k>0){
        int km = k-1, c = km>>6;
        size_t o = ((size_t)b*Nn+km)*Ff+tx;
        pe  = g_PE[o] + g_offE[(b*NCH+c)*Ff+tx];
        pf  = g_PF[o] + g_offF[(b*NCH+c)*Ff+tx];
        pze = g_PzE[b*Nn+km] + g_offzE[b*NCH+c];
        pzf = g_PzF[b*Nn+km] + g_offzF[b*NCH+c];
    }
    float num = Ei*pe + Fi*(TFf - pf);
    float den = Ei*pze + Fi*(TzF - pzf);
    out[((size_t)b*Nn+row)*Ff+tx] = num/den;
}

// ================= launch =================
extern "C" void kernel_launch(void* const* d_in, const int* in_sizes, int n_in,
                              void* d_out, int out_size) {
    const float* h  = (const float*)d_in[0];
    const float* W  = (const float*)d_in[1];
    const float* ai = (const float*)d_in[2];
    const float* aj = (const float*)d_in[3];
    float* out = (float*)d_out;

    cudaFuncSetAttribute(gemm_mma, cudaFuncAttributeMaxDynamicSharedMemorySize, SM_GEMM);

    wa_kernel    <<<32, 256>>>(W, ai, aj);
    uv_kernel    <<<2048, 256>>>(h);
    rank_kernel  <<<dim3(16, Bb), 128>>>();
    gemm_mma     <<<dim3(Nn/128, Bb), 256, SM_GEMM>>>();
    prefix_chunks<<<dim3(NCH, Bb), 128>>>();
    scan_chunks  <<<dim3(Bb, 4), dim3(32,32)>>>();
    finalize     <<<dim3(Nn/8, Bb), dim3(128,8)>>>(out);
}